// round 13
// baseline (speedup 1.0000x reference)
#include <cuda_runtime.h>
#include <cuda_fp16.h>
#include <cstdint>

#define SM_STRIDE 136            // fp16 elems per smem row (conflict-free ldmatrix)

// smem byte offsets (~112 KB -> 2 CTAs/SM)
#define WS_OFF    0                                  // W fp16: 128*136*2 = 34816
#define XS_OFF    34816                              // x fp16: 2 bufs x 34816
#define XS_BUF    34816
#define XN2_OFF   (XS_OFF + 2*XS_BUF)                // float[4][128] ring = 2048
#define DS_OFF    (XN2_OFF + 2048)                   // float[4][128] ring = 2048
#define US_OFF    (DS_OFF + 2048)                    // float[128] u = W^T h
#define HV_OFF    (US_OFF + 512)                     // float[128]
#define RED1_OFF  (HV_OFF + 512)                     // float2[2][8][32] = 4096
#define RED2_OFF  (RED1_OFF + 4096)                  // float[8][32] = 1024
#define SC_OFF    (RED2_OFF + 1024)                  // float[4]
#define SMEM_BYTES (SC_OFF + 16)

#define MINN  1e-15f
#define MAXN  0.996f
#define ATLIM (1.0f - 1e-7f)

#define LDSM4(R, addr)                                                        \
    asm volatile("ldmatrix.sync.aligned.m8n8.x4.shared.b16 {%0,%1,%2,%3}, [%4];" \
                 : "=r"((R)[0]), "=r"((R)[1]), "=r"((R)[2]), "=r"((R)[3])     \
                 : "r"(addr) : "memory")

#define PAIR_BAR() asm volatile("bar.sync %0, 64;" :: "r"(barid) : "memory")

__device__ __forceinline__ void mma16816(float* d, const uint32_t* a, const uint32_t* b) {
    asm volatile(
        "mma.sync.aligned.m16n8k16.row.col.f32.f16.f16.f32 "
        "{%0,%1,%2,%3}, {%4,%5,%6,%7}, {%8,%9}, {%0,%1,%2,%3};"
        : "+f"(d[0]), "+f"(d[1]), "+f"(d[2]), "+f"(d[3])
        : "r"(a[0]), "r"(a[1]), "r"(a[2]), "r"(a[3]), "r"(b[0]), "r"(b[1]));
}

__device__ __forceinline__ float artanh_c(float x) {
    float xc = fminf(x, ATLIM);
    return 0.5f * (log1pf(xc) - log1pf(-xc));
}

__device__ __forceinline__ void row_chain(float S2, float D, float xn2v, float y2,
                                          float& pa, float& pb, float& Lr) {
    float xn  = fmaxf(sqrtf(xn2v), MINN);
    float mxn = fmaxf(sqrtf(S2), MINN);
    float atx = artanh_c(xn);
    float r1  = tanhf(mxn / xn * atx);
    float scale1 = r1 / mxn;
    float resn = r1;
    float pn = fmaxf(resn, MINN);
    if (pn > MAXN) { scale1 *= MAXN / pn; resn = MAXN; }
    float x2 = resn * resn;
    float xy = scale1 * D;
    float num1 = 1.f + 2.f*xy + y2;
    float den  = fmaxf(1.f + 2.f*xy + x2*y2, MINN);
    float aC = num1 / den;
    float bC = (1.f - x2) / den;
    float o2n2 = aC*aC*x2 + 2.f*aC*bC*xy + bC*bC*y2;
    float o2n  = sqrtf(fmaxf(o2n2, 0.f));
    float g = 1.f;
    float pn2 = fmaxf(o2n, MINN);
    if (pn2 > MAXN) { g = MAXN / pn2; pn2 = MAXN; }
    Lr = artanh_c(pn2) / pn2;
    pa = g * aC * scale1;
    pb = g * bC;
}

__device__ __forceinline__ float final_scale(float ps, float Lr) {
    float P  = sqrtf(fmaxf(ps, 0.f));
    float un = fmaxf(Lr * P, MINN);
    float th = tanhf(un);
    float f  = th / un * Lr;
    if (th > MAXN) f *= MAXN / th;
    return f;
}

// fp32x4 -> fp16x4 (rn) into padded-stride smem
__device__ __forceinline__ void store_h16(__half* dst, int row, int col, float4 v) {
    __half2 h01 = __floats2half2_rn(v.x, v.y);
    __half2 h23 = __floats2half2_rn(v.z, v.w);
    uint2 ph;
    ph.x = *reinterpret_cast<uint32_t*>(&h01);
    ph.y = *reinterpret_cast<uint32_t*>(&h23);
    *(uint2*)(dst + row * SM_STRIDE + col) = ph;
}

__global__ void __launch_bounds__(256, 2)
blinear_fused(const float* __restrict__ X, const float* __restrict__ W,
              const float* __restrict__ B, float* __restrict__ OUT, int nTiles)
{
    extern __shared__ char smem[];
    __half* ws    = (__half*)(smem + WS_OFF);
    float* xn2_s  = (float*)(smem + XN2_OFF);   // [4][128] ring
    float* D_s    = (float*)(smem + DS_OFF);    // [4][128] ring
    float* us     = (float*)(smem + US_OFF);
    float* hvec   = (float*)(smem + HV_OFF);
    float2* red1  = (float2*)(smem + RED1_OFF); // [2][8][32]
    float* red2   = (float*)(smem + RED2_OFF);  // [8][32]
    float* SC     = (float*)(smem + SC_OFF);

    const int tid  = threadIdx.x;
    const int lane = tid & 31;
    const int w    = tid >> 5;   // 0..7
    const int pr   = w >> 1;     // pair 0..3 : rows 32*pr .. 32*pr+31
    const int wh   = w & 1;      // col half  : cols 64*wh .. 64*wh+63
    const int tq   = lane & 3;
    const int q    = lane >> 2;
    const int barid = 1 + pr;
    const int rbase = 32*pr + 16*wh;   // this warp's 16 load-rows within the tile
    const int lr   = lane >> 3;        // 0..3
    const int lc   = lane & 7;         // 0..7

    // ---- once per CTA: W (128x128) -> fp16 in smem ----
    #pragma unroll
    for (int j = 0; j < 16; ++j) {
        int row = j * 8 + w;
        float4 wv = *(const float4*)(W + (size_t)row * 128 + lane * 4);
        store_h16(ws, row, lane * 4, wv);
    }

    // ---- once per CTA: hyp_bias h = proj(expmap0(b)) (warp 0) ----
    if (w == 0) {
        float4 bv = *(const float4*)(B + lane * 4);
        float sq = bv.x*bv.x + bv.y*bv.y + bv.z*bv.z + bv.w*bv.w;
        #pragma unroll
        for (int o = 16; o; o >>= 1) sq += __shfl_xor_sync(0xffffffffu, sq, o);
        float bn2 = sq;
        float bn  = fmaxf(sqrtf(bn2), MINN);
        float th  = tanhf(bn);
        float hs  = th / bn;
        float hn  = hs * sqrtf(bn2);
        float pn  = fmaxf(hn, MINN);
        if (pn > MAXN) hs *= MAXN / pn;
        if (lane == 0) SC[0] = hs * hs * bn2;
        *(float4*)(hvec + lane * 4) =
            make_float4(hs*bv.x, hs*bv.y, hs*bv.z, hs*bv.w);
    }
    __syncthreads();

    const float y2 = SC[0];
    const bool hasB = (y2 != 0.0f);   // uniform across grid

    // ---- once per CTA (only if bias nonzero): u = W^T h ----
    if (hasB && tid < 128) {
        float a = 0.f;
        for (int j = 0; j < 128; ++j)
            a = fmaf(hvec[j], W[(size_t)j * 128 + tid], a);
        us[tid] = a;
    }
    __syncthreads();

    uint32_t s_xs0 = (uint32_t)__cvta_generic_to_shared(smem + XS_OFF);
    uint32_t s_ws  = (uint32_t)__cvta_generic_to_shared(ws);

    // A fragment addresses (relative to x buffer base)
    const uint32_t aoff0 = (uint32_t)(((32*pr + (lane & 15)) * SM_STRIDE + (lane >> 4) * 8) * 2);
    const uint32_t aoff1 = aoff0 + 16 * SM_STRIDE * 2;
    // B fragment addresses: 4 n16-groups covering this warp's 64 cols
    const int bg  = lane >> 3;
    const int b_n = ((bg >> 1) << 3) + (lane & 7);
    const int b_k = (bg & 1) * 8;
    uint32_t boff[4];
    #pragma unroll
    for (int g = 0; g < 4; ++g)
        boff[g] = (uint32_t)(((64*wh + 16*g + b_n) * SM_STRIDE + b_k) * 2);

    // per-row exchange bases within a red1 parity buffer
    const int ex_me = (pr*2 + wh    ) * 32;
    const int ex_ot = (pr*2 + (wh^1)) * 32;

    const int colbase = ((lc * 4) + (lr * 8)) & 31;

    // ---- loader: tile tt -> x buffer b, norm ring slot sl ----
    auto load_x = [&](int tt, int b, int sl) {
        __half* xsb  = (__half*)(smem + XS_OFF + b * XS_BUF);
        float* xn2b  = xn2_s + sl * 128;
        float* Db    = D_s   + sl * 128;
        const size_t rowB = (size_t)tt * 128;
        #pragma unroll
        for (int j = 0; j < 4; ++j) {
            const int row = rbase + 4*j + lr;
            float sq = 0.f, dh = 0.f;
            #pragma unroll
            for (int i = 0; i < 4; ++i) {
                const int col = colbase + 32*i;
                float4 v = *(const float4*)(X + (rowB + row) * 128 + col);
                sq = fmaf(v.x, v.x, fmaf(v.y, v.y, fmaf(v.z, v.z, fmaf(v.w, v.w, sq))));
                if (hasB) {
                    float4 u4 = *(const float4*)(us + col);
                    dh = fmaf(v.x, u4.x, fmaf(v.y, u4.y, fmaf(v.z, u4.z, fmaf(v.w, u4.w, dh))));
                }
                store_h16(xsb, row, col, v);
            }
            #pragma unroll
            for (int o = 1; o <= 4; o <<= 1) {
                sq += __shfl_xor_sync(0xffffffffu, sq, o);
                if (hasB) dh += __shfl_xor_sync(0xffffffffu, dh, o);
            }
            if (lc == 0) { xn2b[row] = sq; Db[row] = dh; }
        }
    };

    // ---- prologue: tile_0 into buffer 0 / ring slot 0 ----
    int tile = blockIdx.x;
    if (tile < nTiles) load_x(tile, 0, 0);
    PAIR_BAR();

    // ================= persistent, double-buffered tile loop ================
    for (int i = 0; tile < nTiles; tile += gridDim.x, ++i) {
        const int b  = i & 1;
        const int sl = i & 3;
        const size_t tileRow = (size_t)tile * 128;
        const uint32_t s_xs = s_xs0 + (uint32_t)(b * XS_BUF);
        float2* red1b = red1 + b * 256;

        // ---- MMA: 32 rows x 64 cols, single fp16 term ----
        float acc[2][8][4];
        #pragma unroll
        for (int mt = 0; mt < 2; ++mt)
            #pragma unroll
            for (int nt = 0; nt < 8; ++nt)
                #pragma unroll
                for (int r = 0; r < 4; ++r) acc[mt][nt][r] = 0.f;

        #pragma unroll
        for (int k = 0; k < 8; ++k) {
            const uint32_t kb = k * 32;
            uint32_t ah0[4], ah1[4];
            LDSM4(ah0, s_xs + aoff0 + kb);
            LDSM4(ah1, s_xs + aoff1 + kb);
            uint32_t bh[4][4];
            #pragma unroll
            for (int g = 0; g < 4; ++g)
                LDSM4(bh[g], s_ws + boff[g] + kb);
            #pragma unroll
            for (int nt = 0; nt < 8; ++nt) {
                const int g = nt >> 1, o = (nt & 1) * 2;
                mma16816(acc[0][nt], ah0, &bh[g][o]);
                mma16816(acc[1][nt], ah1, &bh[g][o]);
            }
        }

        // ---- load NEXT tile now: LDG latency hides behind phase1+chain ----
        {
            int tn = tile + gridDim.x;
            if (tn < nTiles) load_x(tn, b ^ 1, (i + 1) & 3);
        }

        // ---- phase 1: per-row sum(mx^2) AND sum(relu(mx)^2); acc<-relu ----
        #pragma unroll
        for (int mt = 0; mt < 2; ++mt) {
            float sq0 = 0.f, r0 = 0.f, sq1 = 0.f, r1 = 0.f;
            #pragma unroll
            for (int nt = 0; nt < 8; ++nt) {
                float v0 = acc[mt][nt][0], v1 = acc[mt][nt][1];
                float v2 = acc[mt][nt][2], v3 = acc[mt][nt][3];
                sq0 = fmaf(v0, v0, fmaf(v1, v1, sq0));
                sq1 = fmaf(v2, v2, fmaf(v3, v3, sq1));
                float p0 = fmaxf(v0, 0.f), p1 = fmaxf(v1, 0.f);
                float p2 = fmaxf(v2, 0.f), p3 = fmaxf(v3, 0.f);
                r0 = fmaf(p0, p0, fmaf(p1, p1, r0));
                r1 = fmaf(p2, p2, fmaf(p3, p3, r1));
                if (!hasB) {  // pre-relu values not needed again on fast path
                    acc[mt][nt][0] = p0; acc[mt][nt][1] = p1;
                    acc[mt][nt][2] = p2; acc[mt][nt][3] = p3;
                }
            }
            #pragma unroll
            for (int o = 1; o <= 2; o <<= 1) {
                sq0 += __shfl_xor_sync(0xffffffffu, sq0, o);
                r0  += __shfl_xor_sync(0xffffffffu, r0,  o);
                sq1 += __shfl_xor_sync(0xffffffffu, sq1, o);
                r1  += __shfl_xor_sync(0xffffffffu, r1,  o);
            }
            if (tq == 0) {
                red1b[ex_me + 16*mt + q]     = make_float2(sq0, r0);
                red1b[ex_me + 16*mt + 8 + q] = make_float2(sq1, r1);
            }
        }

        PAIR_BAR();   // exchange ready + next-tile xs/xn2/D ready

        // ---- lane-parallel scalar chain: lane = local row 0..31 of this pair ----
        float2 aP = red1b[ex_me + lane];
        float2 bP = red1b[ex_ot + lane];
        float S2 = aP.x + bP.x;
        float Rr = aP.y + bP.y;
        float pa, pb, Lr;
        row_chain(S2, hasB ? D_s[sl*128 + 32*pr + lane] : 0.f,
                  xn2_s[sl*128 + 32*pr + lane], y2, pa, pb, Lr);

        if (!hasB) {
            float fac = final_scale(pa * pa * Rr, Lr) * pa;
            float fv[2][2];
            fv[0][0] = __shfl_sync(0xffffffffu, fac, q);
            fv[0][1] = __shfl_sync(0xffffffffu, fac, q + 8);
            fv[1][0] = __shfl_sync(0xffffffffu, fac, q + 16);
            fv[1][1] = __shfl_sync(0xffffffffu, fac, q + 24);
            #pragma unroll
            for (int mt = 0; mt < 2; ++mt)
                #pragma unroll
                for (int rh = 0; rh < 2; ++rh) {
                    const float fs = fv[mt][rh];
                    float* outp = OUT + (tileRow + 32*pr + 16*mt + 8*rh + q) * 128
                                      + 64*wh + 2*tq;
                    #pragma unroll
                    for (int nt = 0; nt < 8; ++nt) {
                        float2 o;
                        o.x = fs * acc[mt][nt][2*rh];       // acc already relu'd
                        o.y = fs * acc[mt][nt][2*rh + 1];
                        *(float2*)(outp + 8*nt) = o;
                    }
                }
        } else {
            // ---- general path: p = relu(pa*mx + pb*h), second exchange ----
            float paM[2][2], pbM[2][2];
            #pragma unroll
            for (int mt = 0; mt < 2; ++mt)
                #pragma unroll
                for (int rh = 0; rh < 2; ++rh) {
                    paM[mt][rh] = __shfl_sync(0xffffffffu, pa, 16*mt + 8*rh + q);
                    pbM[mt][rh] = __shfl_sync(0xffffffffu, pb, 16*mt + 8*rh + q);
                }
            #pragma unroll
            for (int mt = 0; mt < 2; ++mt)
                #pragma unroll
                for (int rh = 0; rh < 2; ++rh) {
                    float ps = 0.f;
                    const float pav = paM[mt][rh], pbv = pbM[mt][rh];
                    #pragma unroll
                    for (int nt = 0; nt < 8; ++nt) {
                        float h0 = hvec[64*wh + 8*nt + 2*tq];
                        float h1 = hvec[64*wh + 8*nt + 2*tq + 1];
                        float p0 = fmaxf(fmaf(pav, acc[mt][nt][2*rh],     pbv * h0), 0.f);
                        float p1 = fmaxf(fmaf(pav, acc[mt][nt][2*rh + 1], pbv * h1), 0.f);
                        acc[mt][nt][2*rh]     = p0;
                        acc[mt][nt][2*rh + 1] = p1;
                        ps = fmaf(p0, p0, fmaf(p1, p1, ps));
                    }
                    ps += __shfl_xor_sync(0xffffffffu, ps, 1);
                    ps += __shfl_xor_sync(0xffffffffu, ps, 2);
                    if (tq == 0) red2[ex_me + 16*mt + 8*rh + q] = ps;
                }
            PAIR_BAR();   // C (bias path only)
            float pst = red2[ex_me + lane] + red2[ex_ot + lane];
            float fs_l = final_scale(pst, Lr);
            float fv[2][2];
            fv[0][0] = __shfl_sync(0xffffffffu, fs_l, q);
            fv[0][1] = __shfl_sync(0xffffffffu, fs_l, q + 8);
            fv[1][0] = __shfl_sync(0xffffffffu, fs_l, q + 16);
            fv[1][1] = __shfl_sync(0xffffffffu, fs_l, q + 24);
            #pragma unroll
            for (int mt = 0; mt < 2; ++mt)
                #pragma unroll
                for (int rh = 0; rh < 2; ++rh) {
                    const float fs = fv[mt][rh];
                    float* outp = OUT + (tileRow + 32*pr + 16*mt + 8*rh + q) * 128
                                      + 64*wh + 2*tq;
                    #pragma unroll
                    for (int nt = 0; nt < 8; ++nt) {
                        float2 o;
                        o.x = fs * acc[mt][nt][2*rh];
                        o.y = fs * acc[mt][nt][2*rh + 1];
                        *(float2*)(outp + 8*nt) = o;
                    }
                }
        }
        // cross-iteration smem reuse: xs 2-deep (bar-ordered), xn2/D 4-deep ring,
        // red1 2-deep, red2 single (bar C ordered) — all safe per barrier analysis
    }
}

extern "C" void kernel_launch(void* const* d_in, const int* in_sizes, int n_in,
                              void* d_out, int out_size) {
    const float* x = (const float*)d_in[0];
    const float* W = (const float*)d_in[1];
    const float* b = (const float*)d_in[2];
    float* out = (float*)d_out;

    int nRows  = in_sizes[0] / 128;      // 524288
    int nTiles = nRows / 128;            // 4096

    int sms = 148;
    cudaDeviceGetAttribute(&sms, cudaDevAttrMultiProcessorCount, 0);
    int grid = 2 * sms;                  // 2 persistent CTAs per SM
    if (grid > nTiles) grid = nTiles;

    cudaFuncSetAttribute(blinear_fused,
                         cudaFuncAttributeMaxDynamicSharedMemorySize, SMEM_BYTES);
    blinear_fused<<<grid, 256, SMEM_BYTES>>>(x, W, b, out, nTiles);
}

// round 14
// speedup vs baseline: 1.0373x; 1.0373x over previous
#include <cuda_runtime.h>
#include <cuda_fp16.h>
#include <cstdint>

#define SM_STRIDE 136            // fp16 elems per smem row (conflict-free ldmatrix)

// smem byte offsets (~112 KB -> 2 CTAs/SM)
#define WS_OFF    0                                  // W fp16: 128*136*2 = 34816
#define XS_OFF    34816                              // x fp16: 2 bufs x 34816
#define XS_BUF    34816
#define XN2_OFF   (XS_OFF + 2*XS_BUF)                // float[4][128] ring = 2048
#define DS_OFF    (XN2_OFF + 2048)                   // float[4][128] ring = 2048
#define US_OFF    (DS_OFF + 2048)                    // float[128] u = W^T h
#define HV_OFF    (US_OFF + 512)                     // float[128]
#define RED1_OFF  (HV_OFF + 512)                     // float2[2][8][32] = 4096
#define RED2_OFF  (RED1_OFF + 4096)                  // float[8][32] = 1024
#define SC_OFF    (RED2_OFF + 1024)                  // float[4]
#define SMEM_BYTES (SC_OFF + 16)

#define MINN  1e-15f
#define MAXN  0.996f
#define ATLIM (1.0f - 1e-7f)

#define LDSM4(R, addr)                                                        \
    asm volatile("ldmatrix.sync.aligned.m8n8.x4.shared.b16 {%0,%1,%2,%3}, [%4];" \
                 : "=r"((R)[0]), "=r"((R)[1]), "=r"((R)[2]), "=r"((R)[3])     \
                 : "r"(addr) : "memory")

#define PAIR_BAR() asm volatile("bar.sync %0, 64;" :: "r"(barid) : "memory")

__device__ __forceinline__ void mma16816(float* d, const uint32_t* a, const uint32_t* b) {
    asm volatile(
        "mma.sync.aligned.m16n8k16.row.col.f32.f16.f16.f32 "
        "{%0,%1,%2,%3}, {%4,%5,%6,%7}, {%8,%9}, {%0,%1,%2,%3};"
        : "+f"(d[0]), "+f"(d[1]), "+f"(d[2]), "+f"(d[3])
        : "r"(a[0]), "r"(a[1]), "r"(a[2]), "r"(a[3]), "r"(b[0]), "r"(b[1]));
}

__device__ __forceinline__ float artanh_c(float x) {
    float xc = fminf(x, ATLIM);
    return 0.5f * (log1pf(xc) - log1pf(-xc));
}

__device__ __forceinline__ void row_chain(float S2, float D, float xn2v, float y2,
                                          float& pa, float& pb, float& Lr) {
    float xn  = fmaxf(sqrtf(xn2v), MINN);
    float mxn = fmaxf(sqrtf(S2), MINN);
    float atx = artanh_c(xn);
    float r1  = tanhf(mxn / xn * atx);
    float scale1 = r1 / mxn;
    float resn = r1;
    float pn = fmaxf(resn, MINN);
    if (pn > MAXN) { scale1 *= MAXN / pn; resn = MAXN; }
    float x2 = resn * resn;
    float xy = scale1 * D;
    float num1 = 1.f + 2.f*xy + y2;
    float den  = fmaxf(1.f + 2.f*xy + x2*y2, MINN);
    float aC = num1 / den;
    float bC = (1.f - x2) / den;
    float o2n2 = aC*aC*x2 + 2.f*aC*bC*xy + bC*bC*y2;
    float o2n  = sqrtf(fmaxf(o2n2, 0.f));
    float g = 1.f;
    float pn2 = fmaxf(o2n, MINN);
    if (pn2 > MAXN) { g = MAXN / pn2; pn2 = MAXN; }
    Lr = artanh_c(pn2) / pn2;
    pa = g * aC * scale1;
    pb = g * bC;
}

__device__ __forceinline__ float final_scale(float ps, float Lr) {
    float P  = sqrtf(fmaxf(ps, 0.f));
    float un = fmaxf(Lr * P, MINN);
    float th = tanhf(un);
    float f  = th / un * Lr;
    if (th > MAXN) f *= MAXN / th;
    return f;
}

// fp32x4 -> fp16x4 (rn) into padded-stride smem
__device__ __forceinline__ void store_h16(__half* dst, int row, int col, float4 v) {
    __half2 h01 = __floats2half2_rn(v.x, v.y);
    __half2 h23 = __floats2half2_rn(v.z, v.w);
    uint2 ph;
    ph.x = *reinterpret_cast<uint32_t*>(&h01);
    ph.y = *reinterpret_cast<uint32_t*>(&h23);
    *(uint2*)(dst + row * SM_STRIDE + col) = ph;
}

__global__ void __launch_bounds__(256, 2)
blinear_fused(const float* __restrict__ X, const float* __restrict__ W,
              const float* __restrict__ B, float* __restrict__ OUT, int nTiles)
{
    extern __shared__ char smem[];
    __half* ws    = (__half*)(smem + WS_OFF);
    float* xn2_s  = (float*)(smem + XN2_OFF);   // [4][128] ring
    float* D_s    = (float*)(smem + DS_OFF);    // [4][128] ring
    float* us     = (float*)(smem + US_OFF);
    float* hvec   = (float*)(smem + HV_OFF);
    float2* red1  = (float2*)(smem + RED1_OFF); // [2][8][32]
    float* red2   = (float*)(smem + RED2_OFF);  // [8][32]
    float* SC     = (float*)(smem + SC_OFF);

    const int tid  = threadIdx.x;
    const int lane = tid & 31;
    const int w    = tid >> 5;   // 0..7
    const int pr   = w >> 1;     // pair 0..3 : rows 32*pr .. 32*pr+31
    const int wh   = w & 1;      // col half  : cols 64*wh .. 64*wh+63
    const int tq   = lane & 3;
    const int q    = lane >> 2;
    const int barid = 1 + pr;
    const int rbase = 32*pr + 16*wh;   // this warp's 16 load-rows within the tile
    const int lr   = lane >> 3;        // 0..3
    const int lc   = lane & 7;         // 0..7

    // ---- once per CTA: W (128x128) -> fp16 in smem ----
    #pragma unroll
    for (int j = 0; j < 16; ++j) {
        int row = j * 8 + w;
        float4 wv = *(const float4*)(W + (size_t)row * 128 + lane * 4);
        store_h16(ws, row, lane * 4, wv);
    }

    // ---- once per CTA: hyp_bias h = proj(expmap0(b)) (warp 0) ----
    if (w == 0) {
        float4 bv = *(const float4*)(B + lane * 4);
        float sq = bv.x*bv.x + bv.y*bv.y + bv.z*bv.z + bv.w*bv.w;
        #pragma unroll
        for (int o = 16; o; o >>= 1) sq += __shfl_xor_sync(0xffffffffu, sq, o);
        float bn2 = sq;
        float bn  = fmaxf(sqrtf(bn2), MINN);
        float th  = tanhf(bn);
        float hs  = th / bn;
        float hn  = hs * sqrtf(bn2);
        float pn  = fmaxf(hn, MINN);
        if (pn > MAXN) hs *= MAXN / pn;
        if (lane == 0) SC[0] = hs * hs * bn2;
        *(float4*)(hvec + lane * 4) =
            make_float4(hs*bv.x, hs*bv.y, hs*bv.z, hs*bv.w);
    }
    __syncthreads();

    const float y2 = SC[0];
    const bool hasB = (y2 != 0.0f);   // uniform across grid

    // ---- once per CTA (only if bias nonzero): u = W^T h ----
    if (hasB && tid < 128) {
        float a = 0.f;
        for (int j = 0; j < 128; ++j)
            a = fmaf(hvec[j], W[(size_t)j * 128 + tid], a);
        us[tid] = a;
    }
    __syncthreads();

    uint32_t s_xs0 = (uint32_t)__cvta_generic_to_shared(smem + XS_OFF);
    uint32_t s_ws  = (uint32_t)__cvta_generic_to_shared(ws);

    // A fragment addresses (relative to x buffer base)
    const uint32_t aoff0 = (uint32_t)(((32*pr + (lane & 15)) * SM_STRIDE + (lane >> 4) * 8) * 2);
    const uint32_t aoff1 = aoff0 + 16 * SM_STRIDE * 2;
    // B fragment addresses: 4 n16-groups covering this warp's 64 cols
    const int bg  = lane >> 3;
    const int b_n = ((bg >> 1) << 3) + (lane & 7);
    const int b_k = (bg & 1) * 8;
    uint32_t boff[4];
    #pragma unroll
    for (int g = 0; g < 4; ++g)
        boff[g] = (uint32_t)(((64*wh + 16*g + b_n) * SM_STRIDE + b_k) * 2);

    // per-row exchange bases within a red1 parity buffer
    const int ex_me = (pr*2 + wh    ) * 32;
    const int ex_ot = (pr*2 + (wh^1)) * 32;

    const int colbase = ((lc * 4) + (lr * 8)) & 31;

    // ---- loader: tile tt -> x buffer b, norm ring slot sl ----
    auto load_x = [&](int tt, int b, int sl) {
        __half* xsb  = (__half*)(smem + XS_OFF + b * XS_BUF);
        float* xn2b  = xn2_s + sl * 128;
        float* Db    = D_s   + sl * 128;
        const size_t rowB = (size_t)tt * 128;
        #pragma unroll
        for (int j = 0; j < 4; ++j) {
            const int row = rbase + 4*j + lr;
            float sq = 0.f, dh = 0.f;
            #pragma unroll
            for (int i = 0; i < 4; ++i) {
                const int col = colbase + 32*i;
                float4 v = *(const float4*)(X + (rowB + row) * 128 + col);
                sq = fmaf(v.x, v.x, fmaf(v.y, v.y, fmaf(v.z, v.z, fmaf(v.w, v.w, sq))));
                if (hasB) {
                    float4 u4 = *(const float4*)(us + col);
                    dh = fmaf(v.x, u4.x, fmaf(v.y, u4.y, fmaf(v.z, u4.z, fmaf(v.w, u4.w, dh))));
                }
                store_h16(xsb, row, col, v);
            }
            #pragma unroll
            for (int o = 1; o <= 4; o <<= 1) {
                sq += __shfl_xor_sync(0xffffffffu, sq, o);
                if (hasB) dh += __shfl_xor_sync(0xffffffffu, dh, o);
            }
            if (lc == 0) { xn2b[row] = sq; Db[row] = dh; }
        }
    };

    // ---- L2 prefetch of a whole warp-slice (8 KB) of tile tt ----
    auto prefetch_x = [&](int tt) {
        if (tt < nTiles) {
            const float* pf = X + ((size_t)tt * 128 + rbase) * 128 + (size_t)lane * 64;
            asm volatile("prefetch.global.L2 [%0];" :: "l"(pf));
            asm volatile("prefetch.global.L2 [%0];" :: "l"(pf + 32));
        }
    };

    // ---- prologue: tile_0 into buffer 0 / ring slot 0; prefetch tile_1 ----
    int tile = blockIdx.x;
    prefetch_x(tile + gridDim.x);
    if (tile < nTiles) load_x(tile, 0, 0);
    PAIR_BAR();

    // ================= persistent, double-buffered tile loop ================
    for (int i = 0; tile < nTiles; tile += gridDim.x, ++i) {
        const int b  = i & 1;
        const int sl = i & 3;
        const size_t tileRow = (size_t)tile * 128;
        const uint32_t s_xs = s_xs0 + (uint32_t)(b * XS_BUF);
        float2* red1b = red1 + b * 256;

        // ---- L2 prefetch tile t+2 FIRST (fire-and-forget, overlaps everything)
        prefetch_x(tile + 2 * gridDim.x);

        // ---- MMA: 32 rows x 64 cols, single fp16 term ----
        float acc[2][8][4];
        #pragma unroll
        for (int mt = 0; mt < 2; ++mt)
            #pragma unroll
            for (int nt = 0; nt < 8; ++nt)
                #pragma unroll
                for (int r = 0; r < 4; ++r) acc[mt][nt][r] = 0.f;

        #pragma unroll
        for (int k = 0; k < 8; ++k) {
            const uint32_t kb = k * 32;
            uint32_t ah0[4], ah1[4];
            LDSM4(ah0, s_xs + aoff0 + kb);
            LDSM4(ah1, s_xs + aoff1 + kb);
            uint32_t bh[4][4];
            #pragma unroll
            for (int g = 0; g < 4; ++g)
                LDSM4(bh[g], s_ws + boff[g] + kb);
            #pragma unroll
            for (int nt = 0; nt < 8; ++nt) {
                const int g = nt >> 1, o = (nt & 1) * 2;
                mma16816(acc[0][nt], ah0, &bh[g][o]);
                mma16816(acc[1][nt], ah1, &bh[g][o]);
            }
        }

        // ---- load NEXT tile now (hits L2 thanks to prefetch last iteration);
        //      its residual latency overlaps phase-1 + chain below ----
        {
            int tn = tile + gridDim.x;
            if (tn < nTiles) load_x(tn, b ^ 1, (i + 1) & 3);
        }

        // ---- phase 1: per-row sum(mx^2) AND sum(relu(mx)^2); acc<-relu ----
        #pragma unroll
        for (int mt = 0; mt < 2; ++mt) {
            float sq0 = 0.f, r0 = 0.f, sq1 = 0.f, r1 = 0.f;
            #pragma unroll
            for (int nt = 0; nt < 8; ++nt) {
                float v0 = acc[mt][nt][0], v1 = acc[mt][nt][1];
                float v2 = acc[mt][nt][2], v3 = acc[mt][nt][3];
                sq0 = fmaf(v0, v0, fmaf(v1, v1, sq0));
                sq1 = fmaf(v2, v2, fmaf(v3, v3, sq1));
                float p0 = fmaxf(v0, 0.f), p1 = fmaxf(v1, 0.f);
                float p2 = fmaxf(v2, 0.f), p3 = fmaxf(v3, 0.f);
                r0 = fmaf(p0, p0, fmaf(p1, p1, r0));
                r1 = fmaf(p2, p2, fmaf(p3, p3, r1));
                if (!hasB) {  // pre-relu values not needed again on fast path
                    acc[mt][nt][0] = p0; acc[mt][nt][1] = p1;
                    acc[mt][nt][2] = p2; acc[mt][nt][3] = p3;
                }
            }
            #pragma unroll
            for (int o = 1; o <= 2; o <<= 1) {
                sq0 += __shfl_xor_sync(0xffffffffu, sq0, o);
                r0  += __shfl_xor_sync(0xffffffffu, r0,  o);
                sq1 += __shfl_xor_sync(0xffffffffu, sq1, o);
                r1  += __shfl_xor_sync(0xffffffffu, r1,  o);
            }
            if (tq == 0) {
                red1b[ex_me + 16*mt + q]     = make_float2(sq0, r0);
                red1b[ex_me + 16*mt + 8 + q] = make_float2(sq1, r1);
            }
        }

        PAIR_BAR();   // exchange ready + next-tile xs/xn2/D ready

        // ---- lane-parallel scalar chain: lane = local row 0..31 of this pair ----
        float2 aP = red1b[ex_me + lane];
        float2 bP = red1b[ex_ot + lane];
        float S2 = aP.x + bP.x;
        float Rr = aP.y + bP.y;
        float pa, pb, Lr;
        row_chain(S2, hasB ? D_s[sl*128 + 32*pr + lane] : 0.f,
                  xn2_s[sl*128 + 32*pr + lane], y2, pa, pb, Lr);

        if (!hasB) {
            float fac = final_scale(pa * pa * Rr, Lr) * pa;
            float fv[2][2];
            fv[0][0] = __shfl_sync(0xffffffffu, fac, q);
            fv[0][1] = __shfl_sync(0xffffffffu, fac, q + 8);
            fv[1][0] = __shfl_sync(0xffffffffu, fac, q + 16);
            fv[1][1] = __shfl_sync(0xffffffffu, fac, q + 24);
            #pragma unroll
            for (int mt = 0; mt < 2; ++mt)
                #pragma unroll
                for (int rh = 0; rh < 2; ++rh) {
                    const float fs = fv[mt][rh];
                    float* outp = OUT + (tileRow + 32*pr + 16*mt + 8*rh + q) * 128
                                      + 64*wh + 2*tq;
                    #pragma unroll
                    for (int nt = 0; nt < 8; ++nt) {
                        float2 o;
                        o.x = fs * acc[mt][nt][2*rh];       // acc already relu'd
                        o.y = fs * acc[mt][nt][2*rh + 1];
                        *(float2*)(outp + 8*nt) = o;
                    }
                }
        } else {
            // ---- general path: p = relu(pa*mx + pb*h), second exchange ----
            float paM[2][2], pbM[2][2];
            #pragma unroll
            for (int mt = 0; mt < 2; ++mt)
                #pragma unroll
                for (int rh = 0; rh < 2; ++rh) {
                    paM[mt][rh] = __shfl_sync(0xffffffffu, pa, 16*mt + 8*rh + q);
                    pbM[mt][rh] = __shfl_sync(0xffffffffu, pb, 16*mt + 8*rh + q);
                }
            #pragma unroll
            for (int mt = 0; mt < 2; ++mt)
                #pragma unroll
                for (int rh = 0; rh < 2; ++rh) {
                    float ps = 0.f;
                    const float pav = paM[mt][rh], pbv = pbM[mt][rh];
                    #pragma unroll
                    for (int nt = 0; nt < 8; ++nt) {
                        float h0 = hvec[64*wh + 8*nt + 2*tq];
                        float h1 = hvec[64*wh + 8*nt + 2*tq + 1];
                        float p0 = fmaxf(fmaf(pav, acc[mt][nt][2*rh],     pbv * h0), 0.f);
                        float p1 = fmaxf(fmaf(pav, acc[mt][nt][2*rh + 1], pbv * h1), 0.f);
                        acc[mt][nt][2*rh]     = p0;
                        acc[mt][nt][2*rh + 1] = p1;
                        ps = fmaf(p0, p0, fmaf(p1, p1, ps));
                    }
                    ps += __shfl_xor_sync(0xffffffffu, ps, 1);
                    ps += __shfl_xor_sync(0xffffffffu, ps, 2);
                    if (tq == 0) red2[ex_me + 16*mt + 8*rh + q] = ps;
                }
            PAIR_BAR();   // C (bias path only)
            float pst = red2[ex_me + lane] + red2[ex_ot + lane];
            float fs_l = final_scale(pst, Lr);
            float fv[2][2];
            fv[0][0] = __shfl_sync(0xffffffffu, fs_l, q);
            fv[0][1] = __shfl_sync(0xffffffffu, fs_l, q + 8);
            fv[1][0] = __shfl_sync(0xffffffffu, fs_l, q + 16);
            fv[1][1] = __shfl_sync(0xffffffffu, fs_l, q + 24);
            #pragma unroll
            for (int mt = 0; mt < 2; ++mt)
                #pragma unroll
                for (int rh = 0; rh < 2; ++rh) {
                    const float fs = fv[mt][rh];
                    float* outp = OUT + (tileRow + 32*pr + 16*mt + 8*rh + q) * 128
                                      + 64*wh + 2*tq;
                    #pragma unroll
                    for (int nt = 0; nt < 8; ++nt) {
                        float2 o;
                        o.x = fs * acc[mt][nt][2*rh];
                        o.y = fs * acc[mt][nt][2*rh + 1];
                        *(float2*)(outp + 8*nt) = o;
                    }
                }
        }
        // cross-iteration smem reuse: xs 2-deep (bar-ordered), xn2/D 4-deep ring,
        // red1 2-deep, red2 single (bar C ordered) — all safe per barrier analysis
    }
}

extern "C" void kernel_launch(void* const* d_in, const int* in_sizes, int n_in,
                              void* d_out, int out_size) {
    const float* x = (const float*)d_in[0];
    const float* W = (const float*)d_in[1];
    const float* b = (const float*)d_in[2];
    float* out = (float*)d_out;

    int nRows  = in_sizes[0] / 128;      // 524288
    int nTiles = nRows / 128;            // 4096

    int sms = 148;
    cudaDeviceGetAttribute(&sms, cudaDevAttrMultiProcessorCount, 0);
    int grid = 2 * sms;                  // 2 persistent CTAs per SM
    if (grid > nTiles) grid = nTiles;

    cudaFuncSetAttribute(blinear_fused,
                         cudaFuncAttributeMaxDynamicSharedMemorySize, SMEM_BYTES);
    blinear_fused<<<grid, 256, SMEM_BYTES>>>(x, W, b, out, nTiles);
}

// round 15
// speedup vs baseline: 1.2870x; 1.2407x over previous
#include <cuda_runtime.h>
#include <cuda_fp16.h>
#include <cstdint>

#define SM_STRIDE 136            // fp16 elems per smem row (conflict-free ldmatrix)

// smem byte offsets (~75 KB -> 2 CTAs/SM)
#define WS_OFF    0                                  // W fp16: 128*136*2 = 34816
#define XS_OFF    34816                              // x fp16: 128 rows
#define XN2_OFF   (XS_OFF + 128 * SM_STRIDE * 2)     // float[128]
#define DS_OFF    (XN2_OFF + 512)                    // float[128]  per-row D = <x,u>
#define US_OFF    (DS_OFF + 512)                     // float[128]  u = W^T h
#define HV_OFF    (US_OFF + 512)                     // float[128]  h (logical order)
#define HP_OFF    (HV_OFF + 512)                     // float[128]  h (mma order)
#define RED1_OFF  (HP_OFF + 512)                     // float2[8][32] = 2048
#define RED2_OFF  (RED1_OFF + 2048)                  // float[8][32] = 1024
#define SC_OFF    (RED2_OFF + 1024)                  // float[4]
#define SMEM_BYTES (SC_OFF + 16)

#define MINN  1e-15f
#define MAXN  0.996f
#define ATLIM (1.0f - 1e-7f)

#define LDSM4(R, addr)                                                        \
    asm volatile("ldmatrix.sync.aligned.m8n8.x4.shared.b16 {%0,%1,%2,%3}, [%4];" \
                 : "=r"((R)[0]), "=r"((R)[1]), "=r"((R)[2]), "=r"((R)[3])     \
                 : "r"(addr) : "memory")

#define PAIR_BAR() asm volatile("bar.sync %0, 64;" :: "r"(barid) : "memory")

__device__ __forceinline__ void mma16816(float* d, const uint32_t* a, const uint32_t* b) {
    asm volatile(
        "mma.sync.aligned.m16n8k16.row.col.f32.f16.f16.f32 "
        "{%0,%1,%2,%3}, {%4,%5,%6,%7}, {%8,%9}, {%0,%1,%2,%3};"
        : "+f"(d[0]), "+f"(d[1]), "+f"(d[2]), "+f"(d[3])
        : "r"(a[0]), "r"(a[1]), "r"(a[2]), "r"(a[3]), "r"(b[0]), "r"(b[1]));
}

// Column permutation: mma col c within a 16-col block maps to logical col f(c)
//   c = blk + m:  m<8: L = blk + 4*(m>>1) + (m&1)
//                 m>=8: L = blk + 4*((m-8)>>1) + 2 + (m&1)
// => thread tq's 4 owned mma cols per 16-block are logical {4tq..4tq+3} (contiguous)
__device__ __forceinline__ int perm_inv(int L) {   // logical -> mma row for W/h staging
    int blk = L & ~15;
    int t = (L >> 2) & 3;
    int u = L & 3;
    return blk + (u < 2 ? 2*t + u : 8 + 2*t + (u - 2));
}

__device__ __forceinline__ float artanh_c(float x) {
    float xc = fminf(x, ATLIM);
    return 0.5f * (log1pf(xc) - log1pf(-xc));
}

__device__ __forceinline__ void row_chain(float S2, float D, float xn2v, float y2,
                                          float& pa, float& pb, float& Lr) {
    float xn  = fmaxf(sqrtf(xn2v), MINN);
    float mxn = fmaxf(sqrtf(S2), MINN);
    float atx = artanh_c(xn);
    float r1  = tanhf(mxn / xn * atx);
    float scale1 = r1 / mxn;
    float resn = r1;
    float pn = fmaxf(resn, MINN);
    if (pn > MAXN) { scale1 *= MAXN / pn; resn = MAXN; }
    float x2 = resn * resn;
    float xy = scale1 * D;
    float num1 = 1.f + 2.f*xy + y2;
    float den  = fmaxf(1.f + 2.f*xy + x2*y2, MINN);
    float aC = num1 / den;
    float bC = (1.f - x2) / den;
    float o2n2 = aC*aC*x2 + 2.f*aC*bC*xy + bC*bC*y2;
    float o2n  = sqrtf(fmaxf(o2n2, 0.f));
    float g = 1.f;
    float pn2 = fmaxf(o2n, MINN);
    if (pn2 > MAXN) { g = MAXN / pn2; pn2 = MAXN; }
    Lr = artanh_c(pn2) / pn2;
    pa = g * aC * scale1;
    pb = g * bC;
}

__device__ __forceinline__ float final_scale(float ps, float Lr) {
    float P  = sqrtf(fmaxf(ps, 0.f));
    float un = fmaxf(Lr * P, MINN);
    float th = tanhf(un);
    float f  = th / un * Lr;
    if (th > MAXN) f *= MAXN / th;
    return f;
}

// fp32x4 -> fp16x4 (rn) into padded-stride smem
__device__ __forceinline__ void store_h16(__half* dst, int row, int col, float4 v) {
    __half2 h01 = __floats2half2_rn(v.x, v.y);
    __half2 h23 = __floats2half2_rn(v.z, v.w);
    uint2 ph;
    ph.x = *reinterpret_cast<uint32_t*>(&h01);
    ph.y = *reinterpret_cast<uint32_t*>(&h23);
    *(uint2*)(dst + row * SM_STRIDE + col) = ph;
}

__global__ void __launch_bounds__(256, 2)
blinear_fused(const float* __restrict__ X, const float* __restrict__ W,
              const float* __restrict__ B, float* __restrict__ OUT, int nTiles)
{
    extern __shared__ char smem[];
    __half* ws    = (__half*)(smem + WS_OFF);
    __half* xs    = (__half*)(smem + XS_OFF);
    float* xn2_s  = (float*)(smem + XN2_OFF);
    float* D_s    = (float*)(smem + DS_OFF);
    float* us     = (float*)(smem + US_OFF);
    float* hvec   = (float*)(smem + HV_OFF);
    float* hperm  = (float*)(smem + HP_OFF);
    float2* red1  = (float2*)(smem + RED1_OFF);
    float* red2   = (float*)(smem + RED2_OFF);
    float* SC     = (float*)(smem + SC_OFF);

    const int tid  = threadIdx.x;
    const int lane = tid & 31;
    const int w    = tid >> 5;   // 0..7
    const int pr   = w >> 1;     // pair 0..3 : rows 32*pr .. 32*pr+31
    const int wh   = w & 1;      // col half  : cols 64*wh .. 64*wh+63
    const int tq   = lane & 3;
    const int q    = lane >> 2;
    const int barid = 1 + pr;
    const int rbase = 32*pr + 16*wh;   // this warp's 16 load-rows within the tile
    const int lr   = lane >> 3;        // 0..3
    const int lc   = lane & 7;         // 0..7

    // ---- once per CTA: W (128x128) -> fp16 in smem, PERMUTED row order ----
    // smem mma-row perm_inv(L) holds logical W row L => each thread's MMA
    // output cols form contiguous logical quads (enables STG.128 epilogue)
    #pragma unroll
    for (int j = 0; j < 16; ++j) {
        int row = j * 8 + w;
        float4 wv = *(const float4*)(W + (size_t)row * 128 + lane * 4);
        store_h16(ws, perm_inv(row), lane * 4, wv);
    }

    // ---- once per CTA: hyp_bias h = proj(expmap0(b)) (warp 0) ----
    if (w == 0) {
        float4 bv = *(const float4*)(B + lane * 4);
        float sq = bv.x*bv.x + bv.y*bv.y + bv.z*bv.z + bv.w*bv.w;
        #pragma unroll
        for (int o = 16; o; o >>= 1) sq += __shfl_xor_sync(0xffffffffu, sq, o);
        float bn2 = sq;
        float bn  = fmaxf(sqrtf(bn2), MINN);
        float th  = tanhf(bn);
        float hs  = th / bn;
        float hn  = hs * sqrtf(bn2);
        float pn  = fmaxf(hn, MINN);
        if (pn > MAXN) hs *= MAXN / pn;
        if (lane == 0) SC[0] = hs * hs * bn2;
        *(float4*)(hvec + lane * 4) =
            make_float4(hs*bv.x, hs*bv.y, hs*bv.z, hs*bv.w);
    }
    __syncthreads();

    const float y2 = SC[0];
    const bool hasB = (y2 != 0.0f);   // uniform across grid

    // ---- h in mma order; u = W^T h (logical, bias path only) ----
    if (tid < 128) {
        hperm[perm_inv(tid)] = hvec[tid];
        if (hasB) {
            float a = 0.f;
            for (int j = 0; j < 128; ++j)
                a = fmaf(hvec[j], W[(size_t)j * 128 + tid], a);
            us[tid] = a;
        }
    }
    __syncthreads();

    uint32_t s_xs = (uint32_t)__cvta_generic_to_shared(xs);
    uint32_t s_ws = (uint32_t)__cvta_generic_to_shared(ws);

    // A fragment addresses: pair rows 32*pr..32*pr+31 (two m16 frags)
    const uint32_t aoff0 = (uint32_t)(((32*pr + (lane & 15)) * SM_STRIDE + (lane >> 4) * 8) * 2);
    const uint32_t aoff1 = aoff0 + 16 * SM_STRIDE * 2;
    // B fragment addresses: 4 n16-groups covering this warp's 64 cols
    const int bg  = lane >> 3;
    const int b_n = ((bg >> 1) << 3) + (lane & 7);
    const int b_k = (bg & 1) * 8;
    uint32_t boff[4];
    #pragma unroll
    for (int g = 0; g < 4; ++g)
        boff[g] = (uint32_t)(((64*wh + 16*g + b_n) * SM_STRIDE + b_k) * 2);

    // per-row exchange bases
    const int ex_me = (pr*2 + wh    ) * 32;
    const int ex_ot = (pr*2 + (wh^1)) * 32;

    const int colbase = ((lc * 4) + (lr * 8)) & 31;

    // ================= persistent tile loop (128-row CTA tiles) =============
    for (int tile = blockIdx.x; tile < nTiles; tile += gridDim.x) {
        const size_t tileRow = (size_t)tile * 128;

        // ---- load 16 rows: 4 row-groups x 8 lanes x 4 chunks (coalesced) ----
        #pragma unroll
        for (int j = 0; j < 4; ++j) {
            const int row = rbase + 4*j + lr;
            float sq = 0.f, dh = 0.f;
            #pragma unroll
            for (int i = 0; i < 4; ++i) {
                const int col = colbase + 32*i;
                float4 v = *(const float4*)(X + (tileRow + row) * 128 + col);
                sq = fmaf(v.x, v.x, fmaf(v.y, v.y, fmaf(v.z, v.z, fmaf(v.w, v.w, sq))));
                if (hasB) {
                    float4 u4 = *(const float4*)(us + col);
                    dh = fmaf(v.x, u4.x, fmaf(v.y, u4.y, fmaf(v.z, u4.z, fmaf(v.w, u4.w, dh))));
                }
                store_h16(xs, row, col, v);
            }
            #pragma unroll
            for (int o = 1; o <= 4; o <<= 1) {
                sq += __shfl_xor_sync(0xffffffffu, sq, o);
                if (hasB) dh += __shfl_xor_sync(0xffffffffu, dh, o);
            }
            if (lc == 0) { xn2_s[row] = sq; D_s[row] = dh; }
        }

        // L2 prefetch next tile's 16 rows for this warp (8 KB)
        {
            int nt2 = tile + gridDim.x;
            if (nt2 < nTiles) {
                const float* pf = X + ((size_t)nt2 * 128 + rbase) * 128
                                    + (size_t)lane * 64;
                asm volatile("prefetch.global.L2 [%0];" :: "l"(pf));
                asm volatile("prefetch.global.L2 [%0];" :: "l"(pf + 32));
            }
        }

        PAIR_BAR();   // A: xs + xn2 + D visible within pair

        // ---- MMA: 32 rows x 64 cols, single fp16 term ----
        float acc[2][8][4];
        #pragma unroll
        for (int mt = 0; mt < 2; ++mt)
            #pragma unroll
            for (int nt = 0; nt < 8; ++nt)
                #pragma unroll
                for (int r = 0; r < 4; ++r) acc[mt][nt][r] = 0.f;

        #pragma unroll
        for (int k = 0; k < 8; ++k) {
            const uint32_t kb = k * 32;
            uint32_t ah0[4], ah1[4];
            LDSM4(ah0, s_xs + aoff0 + kb);
            LDSM4(ah1, s_xs + aoff1 + kb);
            uint32_t bh[4][4];
            #pragma unroll
            for (int g = 0; g < 4; ++g)
                LDSM4(bh[g], s_ws + boff[g] + kb);
            #pragma unroll
            for (int nt = 0; nt < 8; ++nt) {
                const int g = nt >> 1, o = (nt & 1) * 2;
                mma16816(acc[0][nt], ah0, &bh[g][o]);
                mma16816(acc[1][nt], ah1, &bh[g][o]);
            }
        }

        // ---- phase 1: per-row sum(mx^2) AND sum(relu(mx)^2); acc<-relu ----
        #pragma unroll
        for (int mt = 0; mt < 2; ++mt) {
            float sq0 = 0.f, r0 = 0.f, sq1 = 0.f, r1 = 0.f;
            #pragma unroll
            for (int nt = 0; nt < 8; ++nt) {
                float v0 = acc[mt][nt][0], v1 = acc[mt][nt][1];
                float v2 = acc[mt][nt][2], v3 = acc[mt][nt][3];
                sq0 = fmaf(v0, v0, fmaf(v1, v1, sq0));
                sq1 = fmaf(v2, v2, fmaf(v3, v3, sq1));
                float p0 = fmaxf(v0, 0.f), p1 = fmaxf(v1, 0.f);
                float p2 = fmaxf(v2, 0.f), p3 = fmaxf(v3, 0.f);
                r0 = fmaf(p0, p0, fmaf(p1, p1, r0));
                r1 = fmaf(p2, p2, fmaf(p3, p3, r1));
                if (!hasB) {  // pre-relu values not needed again on fast path
                    acc[mt][nt][0] = p0; acc[mt][nt][1] = p1;
                    acc[mt][nt][2] = p2; acc[mt][nt][3] = p3;
                }
            }
            #pragma unroll
            for (int o = 1; o <= 2; o <<= 1) {
                sq0 += __shfl_xor_sync(0xffffffffu, sq0, o);
                r0  += __shfl_xor_sync(0xffffffffu, r0,  o);
                sq1 += __shfl_xor_sync(0xffffffffu, sq1, o);
                r1  += __shfl_xor_sync(0xffffffffu, r1,  o);
            }
            if (tq == 0) {
                red1[ex_me + 16*mt + q]     = make_float2(sq0, r0);
                red1[ex_me + 16*mt + 8 + q] = make_float2(sq1, r1);
            }
        }
        PAIR_BAR();   // B

        // ---- lane-parallel scalar chain: lane = local row 0..31 of this pair ----
        float2 aP = red1[ex_me + lane];
        float2 bP = red1[ex_ot + lane];
        float S2 = aP.x + bP.x;
        float Rr = aP.y + bP.y;
        float pa, pb, Lr;
        row_chain(S2, hasB ? D_s[32*pr + lane] : 0.f,
                  xn2_s[32*pr + lane], y2, pa, pb, Lr);

        if (!hasB) {
            // relu(pa*mx) = pa*relu(mx); fac folds everything into one multiplier
            float fac = final_scale(pa * pa * Rr, Lr) * pa;
            float fv[2][2];
            fv[0][0] = __shfl_sync(0xffffffffu, fac, q);
            fv[0][1] = __shfl_sync(0xffffffffu, fac, q + 8);
            fv[1][0] = __shfl_sync(0xffffffffu, fac, q + 16);
            fv[1][1] = __shfl_sync(0xffffffffu, fac, q + 24);
            #pragma unroll
            for (int mt = 0; mt < 2; ++mt)
                #pragma unroll
                for (int rh = 0; rh < 2; ++rh) {
                    const float fs = fv[mt][rh];
                    float* outp = OUT + (tileRow + 32*pr + 16*mt + 8*rh + q) * 128
                                      + 64*wh + 4*tq;
                    #pragma unroll
                    for (int jj = 0; jj < 4; ++jj) {
                        float4 o;   // permuted layout: contiguous logical quad
                        o.x = fs * acc[mt][2*jj    ][2*rh];
                        o.y = fs * acc[mt][2*jj    ][2*rh + 1];
                        o.z = fs * acc[mt][2*jj + 1][2*rh];
                        o.w = fs * acc[mt][2*jj + 1][2*rh + 1];
                        *(float4*)(outp + 16*jj) = o;
                    }
                }
        } else {
            // ---- general path: p = relu(pa*mx + pb*h), second exchange ----
            float paM[2][2], pbM[2][2];
            #pragma unroll
            for (int mt = 0; mt < 2; ++mt)
                #pragma unroll
                for (int rh = 0; rh < 2; ++rh) {
                    paM[mt][rh] = __shfl_sync(0xffffffffu, pa, 16*mt + 8*rh + q);
                    pbM[mt][rh] = __shfl_sync(0xffffffffu, pb, 16*mt + 8*rh + q);
                }
            #pragma unroll
            for (int mt = 0; mt < 2; ++mt)
                #pragma unroll
                for (int rh = 0; rh < 2; ++rh) {
                    float ps = 0.f;
                    const float pav = paM[mt][rh], pbv = pbM[mt][rh];
                    #pragma unroll
                    for (int nt = 0; nt < 8; ++nt) {
                        float h0 = hperm[64*wh + 8*nt + 2*tq];      // mma order
                        float h1 = hperm[64*wh + 8*nt + 2*tq + 1];
                        float p0 = fmaxf(fmaf(pav, acc[mt][nt][2*rh],     pbv * h0), 0.f);
                        float p1 = fmaxf(fmaf(pav, acc[mt][nt][2*rh + 1], pbv * h1), 0.f);
                        acc[mt][nt][2*rh]     = p0;
                        acc[mt][nt][2*rh + 1] = p1;
                        ps = fmaf(p0, p0, fmaf(p1, p1, ps));
                    }
                    ps += __shfl_xor_sync(0xffffffffu, ps, 1);
                    ps += __shfl_xor_sync(0xffffffffu, ps, 2);
                    if (tq == 0) red2[ex_me + 16*mt + 8*rh + q] = ps;
                }
            PAIR_BAR();   // C (bias path only)
            float pst = red2[ex_me + lane] + red2[ex_ot + lane];
            float fs_l = final_scale(pst, Lr);
            float fv[2][2];
            fv[0][0] = __shfl_sync(0xffffffffu, fs_l, q);
            fv[0][1] = __shfl_sync(0xffffffffu, fs_l, q + 8);
            fv[1][0] = __shfl_sync(0xffffffffu, fs_l, q + 16);
            fv[1][1] = __shfl_sync(0xffffffffu, fs_l, q + 24);
            #pragma unroll
            for (int mt = 0; mt < 2; ++mt)
                #pragma unroll
                for (int rh = 0; rh < 2; ++rh) {
                    const float fs = fv[mt][rh];
                    float* outp = OUT + (tileRow + 32*pr + 16*mt + 8*rh + q) * 128
                                      + 64*wh + 4*tq;
                    #pragma unroll
                    for (int jj = 0; jj < 4; ++jj) {
                        float4 o;
                        o.x = fs * acc[mt][2*jj    ][2*rh];
                        o.y = fs * acc[mt][2*jj    ][2*rh + 1];
                        o.z = fs * acc[mt][2*jj + 1][2*rh];
                        o.w = fs * acc[mt][2*jj + 1][2*rh + 1];
                        *(float4*)(outp + 16*jj) = o;
                    }
                }
        }
        // cross-iteration smem reuse is ordered by the pair barriers
    }
}

extern "C" void kernel_launch(void* const* d_in, const int* in_sizes, int n_in,
                              void* d_out, int out_size) {
    const float* x = (const float*)d_in[0];
    const float* W = (const float*)d_in[1];
    const float* b = (const float*)d_in[2];
    float* out = (float*)d_out;

    int nRows  = in_sizes[0] / 128;      // 524288
    int nTiles = nRows / 128;            // 4096

    int sms = 148;
    cudaDeviceGetAttribute(&sms, cudaDevAttrMultiProcessorCount, 0);
    int grid = 2 * sms;                  // 2 persistent CTAs per SM
    if (grid > nTiles) grid = nTiles;

    cudaFuncSetAttribute(blinear_fused,
                         cudaFuncAttributeMaxDynamicSharedMemorySize, SMEM_BYTES);
    blinear_fused<<<grid, 256, SMEM_BYTES>>>(x, W, b, out, nTiles);
}

// round 16
// speedup vs baseline: 1.3007x; 1.0106x over previous
#include <cuda_runtime.h>
#include <cuda_fp16.h>
#include <cstdint>

#define SM_STRIDE 136            // fp16 elems per smem row (conflict-free ldmatrix)

// smem byte offsets (~75 KB -> 2 CTAs/SM)
#define WS_OFF    0                                  // W fp16: 128*136*2 = 34816
#define XS_OFF    34816                              // x fp16: 128 rows
#define XN2_OFF   (XS_OFF + 128 * SM_STRIDE * 2)     // float[128]
#define DS_OFF    (XN2_OFF + 512)                    // float[128]  per-row D = <x,u>
#define US_OFF    (DS_OFF + 512)                     // float[128]  u = W^T h
#define HV_OFF    (US_OFF + 512)                     // float[128]  h (logical order)
#define HP_OFF    (HV_OFF + 512)                     // float[128]  h (mma order)
#define RED1_OFF  (HP_OFF + 512)                     // float2[8][32] = 2048
#define RED2_OFF  (RED1_OFF + 2048)                  // float[8][32] = 1024
#define SC_OFF    (RED2_OFF + 1024)                  // float[4]
#define SMEM_BYTES (SC_OFF + 16)

#define MINN  1e-15f
#define MAXN  0.996f
#define ATLIM (1.0f - 1e-7f)

#define LDSM4(R, addr)                                                        \
    asm volatile("ldmatrix.sync.aligned.m8n8.x4.shared.b16 {%0,%1,%2,%3}, [%4];" \
                 : "=r"((R)[0]), "=r"((R)[1]), "=r"((R)[2]), "=r"((R)[3])     \
                 : "r"(addr) : "memory")

#define PAIR_BAR() asm volatile("bar.sync %0, 64;" :: "r"(barid) : "memory")

__device__ __forceinline__ void mma16816(float* d, const uint32_t* a, const uint32_t* b) {
    asm volatile(
        "mma.sync.aligned.m16n8k16.row.col.f32.f16.f16.f32 "
        "{%0,%1,%2,%3}, {%4,%5,%6,%7}, {%8,%9}, {%0,%1,%2,%3};"
        : "+f"(d[0]), "+f"(d[1]), "+f"(d[2]), "+f"(d[3])
        : "r"(a[0]), "r"(a[1]), "r"(a[2]), "r"(a[3]), "r"(b[0]), "r"(b[1]));
}

// Column permutation: thread tq's 4 owned mma cols per 16-block are logical
// {4tq..4tq+3} (contiguous) -> enables STG.128 epilogue.
__device__ __forceinline__ int perm_inv(int L) {   // logical -> mma row for W/h staging
    int blk = L & ~15;
    int t = (L >> 2) & 3;
    int u = L & 3;
    return blk + (u < 2 ? 2*t + u : 8 + 2*t + (u - 2));
}

__device__ __forceinline__ float artanh_c(float x) {
    float xc = fminf(x, ATLIM);
    return 0.5f * (log1pf(xc) - log1pf(-xc));
}

__device__ __forceinline__ void row_chain(float S2, float D, float xn2v, float y2,
                                          float& pa, float& pb, float& Lr) {
    float xn  = fmaxf(sqrtf(xn2v), MINN);
    float mxn = fmaxf(sqrtf(S2), MINN);
    float atx = artanh_c(xn);
    float r1  = tanhf(mxn / xn * atx);
    float scale1 = r1 / mxn;
    float resn = r1;
    float pn = fmaxf(resn, MINN);
    if (pn > MAXN) { scale1 *= MAXN / pn; resn = MAXN; }
    float x2 = resn * resn;
    float xy = scale1 * D;
    float num1 = 1.f + 2.f*xy + y2;
    float den  = fmaxf(1.f + 2.f*xy + x2*y2, MINN);
    float aC = num1 / den;
    float bC = (1.f - x2) / den;
    float o2n2 = aC*aC*x2 + 2.f*aC*bC*xy + bC*bC*y2;
    float o2n  = sqrtf(fmaxf(o2n2, 0.f));
    float g = 1.f;
    float pn2 = fmaxf(o2n, MINN);
    if (pn2 > MAXN) { g = MAXN / pn2; pn2 = MAXN; }
    Lr = artanh_c(pn2) / pn2;
    pa = g * aC * scale1;
    pb = g * bC;
}

__device__ __forceinline__ float final_scale(float ps, float Lr) {
    float P  = sqrtf(fmaxf(ps, 0.f));
    float un = fmaxf(Lr * P, MINN);
    float th = tanhf(un);
    float f  = th / un * Lr;
    if (th > MAXN) f *= MAXN / th;
    return f;
}

// fp32x4 -> fp16x4 (rn) into padded-stride smem
__device__ __forceinline__ void store_h16(__half* dst, int row, int col, float4 v) {
    __half2 h01 = __floats2half2_rn(v.x, v.y);
    __half2 h23 = __floats2half2_rn(v.z, v.w);
    uint2 ph;
    ph.x = *reinterpret_cast<uint32_t*>(&h01);
    ph.y = *reinterpret_cast<uint32_t*>(&h23);
    *(uint2*)(dst + row * SM_STRIDE + col) = ph;
}

__global__ void __launch_bounds__(256, 2)
blinear_fused(const float* __restrict__ X, const float* __restrict__ W,
              const float* __restrict__ B, float* __restrict__ OUT, int nTiles)
{
    extern __shared__ char smem[];
    __half* ws    = (__half*)(smem + WS_OFF);
    __half* xs    = (__half*)(smem + XS_OFF);
    float* xn2_s  = (float*)(smem + XN2_OFF);
    float* D_s    = (float*)(smem + DS_OFF);
    float* us     = (float*)(smem + US_OFF);
    float* hvec   = (float*)(smem + HV_OFF);
    float* hperm  = (float*)(smem + HP_OFF);
    float2* red1  = (float2*)(smem + RED1_OFF);
    float* red2   = (float*)(smem + RED2_OFF);
    float* SC     = (float*)(smem + SC_OFF);

    const int tid  = threadIdx.x;
    const int lane = tid & 31;
    const int w    = tid >> 5;   // 0..7
    const int pr   = w >> 1;     // pair 0..3 : rows 32*pr .. 32*pr+31
    const int wh   = w & 1;      // col half  : cols 64*wh .. 64*wh+63
    const int tq   = lane & 3;
    const int q    = lane >> 2;
    const int barid = 1 + pr;
    const int rbase = 32*pr + 16*wh;   // this warp's 16 load-rows within the tile
    const int lr   = lane >> 3;        // 0..3
    const int lc   = lane & 7;         // 0..7

    // ---- once per CTA: W (128x128) -> fp16 in smem, PERMUTED row order ----
    #pragma unroll
    for (int j = 0; j < 16; ++j) {
        int row = j * 8 + w;
        float4 wv = *(const float4*)(W + (size_t)row * 128 + lane * 4);
        store_h16(ws, perm_inv(row), lane * 4, wv);
    }

    // ---- once per CTA: hyp_bias h = proj(expmap0(b)) (warp 0) ----
    if (w == 0) {
        float4 bv = *(const float4*)(B + lane * 4);
        float sq = bv.x*bv.x + bv.y*bv.y + bv.z*bv.z + bv.w*bv.w;
        #pragma unroll
        for (int o = 16; o; o >>= 1) sq += __shfl_xor_sync(0xffffffffu, sq, o);
        float bn2 = sq;
        float bn  = fmaxf(sqrtf(bn2), MINN);
        float th  = tanhf(bn);
        float hs  = th / bn;
        float hn  = hs * sqrtf(bn2);
        float pn  = fmaxf(hn, MINN);
        if (pn > MAXN) hs *= MAXN / pn;
        if (lane == 0) SC[0] = hs * hs * bn2;
        *(float4*)(hvec + lane * 4) =
            make_float4(hs*bv.x, hs*bv.y, hs*bv.z, hs*bv.w);
    }
    __syncthreads();

    const float y2 = SC[0];
    const bool hasB = (y2 != 0.0f);   // uniform across grid

    // ---- h in mma order; u = W^T h (logical, bias path only) ----
    if (tid < 128) {
        hperm[perm_inv(tid)] = hvec[tid];
        if (hasB) {
            float a = 0.f;
            for (int j = 0; j < 128; ++j)
                a = fmaf(hvec[j], W[(size_t)j * 128 + tid], a);
            us[tid] = a;
        }
    }
    __syncthreads();

    uint32_t s_xs = (uint32_t)__cvta_generic_to_shared(xs);
    uint32_t s_ws = (uint32_t)__cvta_generic_to_shared(ws);

    // A fragment addresses: pair rows 32*pr..32*pr+31 (two m16 frags)
    const uint32_t aoff0 = (uint32_t)(((32*pr + (lane & 15)) * SM_STRIDE + (lane >> 4) * 8) * 2);
    const uint32_t aoff1 = aoff0 + 16 * SM_STRIDE * 2;
    // B fragment addresses: 4 n16-groups covering this warp's 64 cols
    const int bg  = lane >> 3;
    const int b_n = ((bg >> 1) << 3) + (lane & 7);
    const int b_k = (bg & 1) * 8;
    uint32_t boff[4];
    #pragma unroll
    for (int g = 0; g < 4; ++g)
        boff[g] = (uint32_t)(((64*wh + 16*g + b_n) * SM_STRIDE + b_k) * 2);

    // per-row exchange bases
    const int ex_me = (pr*2 + wh    ) * 32;
    const int ex_ot = (pr*2 + (wh^1)) * 32;

    const int colbase = ((lc * 4) + (lr * 8)) & 31;

    // ================= persistent tile loop (128-row CTA tiles) =============
    for (int tile = blockIdx.x; tile < nTiles; tile += gridDim.x) {
        const size_t tileRow = (size_t)tile * 128;

        // ---- BATCHED load: issue all 16 LDG.128 first (MLP=16, one L2 wait),
        //      then convert/reduce/STS. X read once -> streaming (__ldcs). ----
        float4 xr[16];
        #pragma unroll
        for (int j = 0; j < 4; ++j) {
            const int row = rbase + 4*j + lr;
            #pragma unroll
            for (int i = 0; i < 4; ++i) {
                const int col = colbase + 32*i;
                xr[j*4 + i] = __ldcs((const float4*)(X + (tileRow + row) * 128 + col));
            }
        }

        // L2 prefetch next tile's 16 rows for this warp (8 KB) — issue early
        {
            int nt2 = tile + gridDim.x;
            if (nt2 < nTiles) {
                const float* pf = X + ((size_t)nt2 * 128 + rbase) * 128
                                    + (size_t)lane * 64;
                asm volatile("prefetch.global.L2 [%0];" :: "l"(pf));
                asm volatile("prefetch.global.L2 [%0];" :: "l"(pf + 32));
            }
        }

        #pragma unroll
        for (int j = 0; j < 4; ++j) {
            const int row = rbase + 4*j + lr;
            float sq = 0.f, dh = 0.f;
            #pragma unroll
            for (int i = 0; i < 4; ++i) {
                const int col = colbase + 32*i;
                float4 v = xr[j*4 + i];
                sq = fmaf(v.x, v.x, fmaf(v.y, v.y, fmaf(v.z, v.z, fmaf(v.w, v.w, sq))));
                if (hasB) {
                    float4 u4 = *(const float4*)(us + col);
                    dh = fmaf(v.x, u4.x, fmaf(v.y, u4.y, fmaf(v.z, u4.z, fmaf(v.w, u4.w, dh))));
                }
                store_h16(xs, row, col, v);
            }
            #pragma unroll
            for (int o = 1; o <= 4; o <<= 1) {
                sq += __shfl_xor_sync(0xffffffffu, sq, o);
                if (hasB) dh += __shfl_xor_sync(0xffffffffu, dh, o);
            }
            if (lc == 0) { xn2_s[row] = sq; D_s[row] = dh; }
        }

        PAIR_BAR();   // A: xs + xn2 + D visible within pair

        // ---- MMA: 32 rows x 64 cols, single fp16 term ----
        float acc[2][8][4];
        #pragma unroll
        for (int mt = 0; mt < 2; ++mt)
            #pragma unroll
            for (int nt = 0; nt < 8; ++nt)
                #pragma unroll
                for (int r = 0; r < 4; ++r) acc[mt][nt][r] = 0.f;

        #pragma unroll
        for (int k = 0; k < 8; ++k) {
            const uint32_t kb = k * 32;
            uint32_t ah0[4], ah1[4];
            LDSM4(ah0, s_xs + aoff0 + kb);
            LDSM4(ah1, s_xs + aoff1 + kb);
            uint32_t bh[4][4];
            #pragma unroll
            for (int g = 0; g < 4; ++g)
                LDSM4(bh[g], s_ws + boff[g] + kb);
            #pragma unroll
            for (int nt = 0; nt < 8; ++nt) {
                const int g = nt >> 1, o = (nt & 1) * 2;
                mma16816(acc[0][nt], ah0, &bh[g][o]);
                mma16816(acc[1][nt], ah1, &bh[g][o]);
            }
        }

        // ---- phase 1: per-row sum(mx^2) AND sum(relu(mx)^2); acc<-relu ----
        #pragma unroll
        for (int mt = 0; mt < 2; ++mt) {
            float sq0 = 0.f, r0 = 0.f, sq1 = 0.f, r1 = 0.f;
            #pragma unroll
            for (int nt = 0; nt < 8; ++nt) {
                float v0 = acc[mt][nt][0], v1 = acc[mt][nt][1];
                float v2 = acc[mt][nt][2], v3 = acc[mt][nt][3];
                sq0 = fmaf(v0, v0, fmaf(v1, v1, sq0));
                sq1 = fmaf(v2, v2, fmaf(v3, v3, sq1));
                float p0 = fmaxf(v0, 0.f), p1 = fmaxf(v1, 0.f);
                float p2 = fmaxf(v2, 0.f), p3 = fmaxf(v3, 0.f);
                r0 = fmaf(p0, p0, fmaf(p1, p1, r0));
                r1 = fmaf(p2, p2, fmaf(p3, p3, r1));
                if (!hasB) {
                    acc[mt][nt][0] = p0; acc[mt][nt][1] = p1;
                    acc[mt][nt][2] = p2; acc[mt][nt][3] = p3;
                }
            }
            #pragma unroll
            for (int o = 1; o <= 2; o <<= 1) {
                sq0 += __shfl_xor_sync(0xffffffffu, sq0, o);
                r0  += __shfl_xor_sync(0xffffffffu, r0,  o);
                sq1 += __shfl_xor_sync(0xffffffffu, sq1, o);
                r1  += __shfl_xor_sync(0xffffffffu, r1,  o);
            }
            if (tq == 0) {
                red1[ex_me + 16*mt + q]     = make_float2(sq0, r0);
                red1[ex_me + 16*mt + 8 + q] = make_float2(sq1, r1);
            }
        }
        PAIR_BAR();   // B

        // ---- lane-parallel scalar chain: lane = local row 0..31 of this pair ----
        float2 aP = red1[ex_me + lane];
        float2 bP = red1[ex_ot + lane];
        float S2 = aP.x + bP.x;
        float Rr = aP.y + bP.y;
        float pa, pb, Lr;
        row_chain(S2, hasB ? D_s[32*pr + lane] : 0.f,
                  xn2_s[32*pr + lane], y2, pa, pb, Lr);

        if (!hasB) {
            float fac = final_scale(pa * pa * Rr, Lr) * pa;
            float fv[2][2];
            fv[0][0] = __shfl_sync(0xffffffffu, fac, q);
            fv[0][1] = __shfl_sync(0xffffffffu, fac, q + 8);
            fv[1][0] = __shfl_sync(0xffffffffu, fac, q + 16);
            fv[1][1] = __shfl_sync(0xffffffffu, fac, q + 24);
            #pragma unroll
            for (int mt = 0; mt < 2; ++mt)
                #pragma unroll
                for (int rh = 0; rh < 2; ++rh) {
                    const float fs = fv[mt][rh];
                    float* outp = OUT + (tileRow + 32*pr + 16*mt + 8*rh + q) * 128
                                      + 64*wh + 4*tq;
                    #pragma unroll
                    for (int jj = 0; jj < 4; ++jj) {
                        float4 o;   // permuted layout: contiguous logical quad
                        o.x = fs * acc[mt][2*jj    ][2*rh];
                        o.y = fs * acc[mt][2*jj    ][2*rh + 1];
                        o.z = fs * acc[mt][2*jj + 1][2*rh];
                        o.w = fs * acc[mt][2*jj + 1][2*rh + 1];
                        __stcs((float4*)(outp + 16*jj), o);   // streaming store
                    }
                }
        } else {
            float paM[2][2], pbM[2][2];
            #pragma unroll
            for (int mt = 0; mt < 2; ++mt)
                #pragma unroll
                for (int rh = 0; rh < 2; ++rh) {
                    paM[mt][rh] = __shfl_sync(0xffffffffu, pa, 16*mt + 8*rh + q);
                    pbM[mt][rh] = __shfl_sync(0xffffffffu, pb, 16*mt + 8*rh + q);
                }
            #pragma unroll
            for (int mt = 0; mt < 2; ++mt)
                #pragma unroll
                for (int rh = 0; rh < 2; ++rh) {
                    float ps = 0.f;
                    const float pav = paM[mt][rh], pbv = pbM[mt][rh];
                    #pragma unroll
                    for (int nt = 0; nt < 8; ++nt) {
                        float h0 = hperm[64*wh + 8*nt + 2*tq];
                        float h1 = hperm[64*wh + 8*nt + 2*tq + 1];
                        float p0 = fmaxf(fmaf(pav, acc[mt][nt][2*rh],     pbv * h0), 0.f);
                        float p1 = fmaxf(fmaf(pav, acc[mt][nt][2*rh + 1], pbv * h1), 0.f);
                        acc[mt][nt][2*rh]     = p0;
                        acc[mt][nt][2*rh + 1] = p1;
                        ps = fmaf(p0, p0, fmaf(p1, p1, ps));
                    }
                    ps += __shfl_xor_sync(0xffffffffu, ps, 1);
                    ps += __shfl_xor_sync(0xffffffffu, ps, 2);
                    if (tq == 0) red2[ex_me + 16*mt + 8*rh + q] = ps;
                }
            PAIR_BAR();   // C (bias path only)
            float pst = red2[ex_me + lane] + red2[ex_ot + lane];
            float fs_l = final_scale(pst, Lr);
            float fv[2][2];
            fv[0][0] = __shfl_sync(0xffffffffu, fs_l, q);
            fv[0][1] = __shfl_sync(0xffffffffu, fs_l, q + 8);
            fv[1][0] = __shfl_sync(0xffffffffu, fs_l, q + 16);
            fv[1][1] = __shfl_sync(0xffffffffu, fs_l, q + 24);
            #pragma unroll
            for (int mt = 0; mt < 2; ++mt)
                #pragma unroll
                for (int rh = 0; rh < 2; ++rh) {
                    const float fs = fv[mt][rh];
                    float* outp = OUT + (tileRow + 32*pr + 16*mt + 8*rh + q) * 128
                                      + 64*wh + 4*tq;
                    #pragma unroll
                    for (int jj = 0; jj < 4; ++jj) {
                        float4 o;
                        o.x = fs * acc[mt][2*jj    ][2*rh];
                        o.y = fs * acc[mt][2*jj    ][2*rh + 1];
                        o.z = fs * acc[mt][2*jj + 1][2*rh];
                        o.w = fs * acc[mt][2*jj + 1][2*rh + 1];
                        __stcs((float4*)(outp + 16*jj), o);
                    }
                }
        }
        // cross-iteration smem reuse is ordered by the pair barriers
    }
}

extern "C" void kernel_launch(void* const* d_in, const int* in_sizes, int n_in,
                              void* d_out, int out_size) {
    const float* x = (const float*)d_in[0];
    const float* W = (const float*)d_in[1];
    const float* b = (const float*)d_in[2];
    float* out = (float*)d_out;

    int nRows  = in_sizes[0] / 128;      // 524288
    int nTiles = nRows / 128;            // 4096

    int sms = 148;
    cudaDeviceGetAttribute(&sms, cudaDevAttrMultiProcessorCount, 0);
    int grid = 2 * sms;                  // 2 persistent CTAs per SM
    if (grid > nTiles) grid = nTiles;

    cudaFuncSetAttribute(blinear_fused,
                         cudaFuncAttributeMaxDynamicSharedMemorySize, SMEM_BYTES);
    blinear_fused<<<grid, 256, SMEM_BYTES>>>(x, W, b, out, nTiles);
}